// round 1
// baseline (speedup 1.0000x reference)
#include <cuda_runtime.h>
#include <math.h>

// ---------------------------------------------------------------------------
// Lookup_8710193676603: RAFT correlation pyramid lookup.
//   feat1 [4,256,64,64] f32, feat2 [4,256,64,64] f32, flow [4,2,64,64] f32
//   out   [4,64,64,4,41] f32
// Key identity: bilinear(pool_k(corr)) == dot(f1_pix, pool_k(f2)_corner)/16,
// so we never build the 268MB corr volume. We build a channel-last pooled
// f2 pyramid, then per (pixel, level) compute corner dots in a <=10x10 grid
// and combine with bilinear weights.
// ---------------------------------------------------------------------------

#define NB 4
#define NC 256
#define NP 4096           // 64*64 pixels per batch

// device scratch (module-static, no runtime allocation)
static __device__ float g_f1t[(size_t)NB * NP * NC];            // [B,64,64,C], pre-scaled by 1/16
static __device__ float g_f2l[5570560];                          // pyramid, channel-last
// level offsets (floats): lvl0 [B,64,64,C], lvl1 [B,32,32,C], lvl2 [B,16,16,C], lvl3 [B,8,8,C]
__device__ const int g_lvloff[4] = {0, 4194304, 5242880, 5505024};

__device__ const float g_dy[41] = {
  -4.f,
  -3.f,-3.f,-3.f,
  -2.f,-2.f,-2.f,-2.f,-2.f,
  -1.f,-1.f,-1.f,-1.f,-1.f,-1.f,-1.f,
   0.f, 0.f, 0.f, 0.f, 0.f, 0.f, 0.f, 0.f, 0.f,
   1.f, 1.f, 1.f, 1.f, 1.f, 1.f, 1.f,
   2.f, 2.f, 2.f, 2.f, 2.f,
   3.f, 3.f, 3.f,
   4.f};
__device__ const float g_dx[41] = {
   0.f,
  -1.f, 0.f, 1.f,
  -2.f,-1.f, 0.f, 1.f, 2.f,
  -3.f,-2.f,-1.f, 0.f, 1.f, 2.f, 3.f,
  -4.f,-3.f,-2.f,-1.f, 0.f, 1.f, 2.f, 3.f, 4.f,
  -3.f,-2.f,-1.f, 0.f, 1.f, 2.f, 3.f,
  -2.f,-1.f, 0.f, 1.f, 2.f,
  -1.f, 0.f, 1.f,
   0.f};

// ---- transpose [B,C,64,64] -> [B,64,64,C], times scale ----------------------
__global__ void transpose_cl(const float* __restrict__ in, float* __restrict__ out,
                             float scale) {
    __shared__ float tile[64][65];
    int cc  = blockIdx.x & 3;          // channel chunk (64 channels)
    int i   = (blockIdx.x >> 2) & 63;  // row
    int b   = blockIdx.x >> 8;
    int tid = threadIdx.x;
#pragma unroll
    for (int t = 0; t < 16; t++) {
        int idx = tid + t * 256;
        int cl = idx >> 6, jj = idx & 63;
        tile[cl][jj] = in[(((b * 256 + cc * 64 + cl) * 64 + i) * 64) + jj] * scale;
    }
    __syncthreads();
#pragma unroll
    for (int t = 0; t < 16; t++) {
        int idx = tid + t * 256;
        int jj = idx >> 6, cl = idx & 63;
        out[((b * 64 + i) * 64 + jj) * 256 + cc * 64 + cl] = tile[cl][jj];
    }
}

// ---- 2x2 avg pool in channel-last layout, float4-vectorized ----------------
__global__ void pool2(const float4* __restrict__ in, float4* __restrict__ out,
                      int hin, int total) {
    int idx = blockIdx.x * blockDim.x + threadIdx.x;
    if (idx >= total) return;
    int hout = hin >> 1;
    int c4 = idx & 63;
    int r  = idx >> 6;
    int x  = r % hout; r /= hout;
    int y  = r % hout;
    int b  = r / hout;
    const float4* p00 = in + (((size_t)(b * hin + 2 * y) * hin + 2 * x) * 64) + c4;
    const float4* p01 = p00 + 64;
    const float4* p10 = p00 + (size_t)hin * 64;
    const float4* p11 = p10 + 64;
    float4 a = *p00, bb = *p01, c = *p10, d = *p11, o;
    o.x = 0.25f * (a.x + bb.x + c.x + d.x);
    o.y = 0.25f * (a.y + bb.y + c.y + d.y);
    o.z = 0.25f * (a.z + bb.z + c.z + d.z);
    o.w = 0.25f * (a.w + bb.w + c.w + d.w);
    out[idx] = o;
}

// ---- main lookup: one warp per (pixel, level) -------------------------------
__global__ __launch_bounds__(256) void lookup_main(const float* __restrict__ flow,
                                                   float* __restrict__ out) {
    __shared__ float sd[8][100];
    int lane = threadIdx.x & 31;
    int warp = threadIdx.x >> 5;
    int g = blockIdx.x * 8 + warp;          // 65536 total, exact
    int k = g & 3;                          // pyramid level
    int p = g >> 2;                         // pixel id
    int b = p >> 12;
    int i = (p >> 6) & 63;
    int j = p & 63;

    // f1 fragment: lane holds channels [lane*8, lane*8+8)
    const float4* f1p = reinterpret_cast<const float4*>(g_f1t + (size_t)p * 256 + lane * 8);
    float4 a0 = f1p[0], a1 = f1p[1];

    float fy = flow[(b * 2 + 0) * 4096 + i * 64 + j];
    float fx = flow[(b * 2 + 1) * 4096 + i * 64 + j];
    int   h   = 64 >> k;
    float sc  = (float)(h - 1) / (float)h;
    float inv = 1.0f / (float)(1 << k);
    float yc = ((float)i + fy) * inv;
    float xc = ((float)j + fx) * inv;
    int y0min = (int)floorf((yc - 4.0f) * sc);
    int x0min = (int)floorf((xc - 4.0f) * sc);

    float* sw = sd[warp];
    sw[lane] = 0.f; sw[lane + 32] = 0.f; sw[lane + 64] = 0.f;
    if (lane < 4) sw[96 + lane] = 0.f;
    __syncwarp();

    int ry0 = max(0, -y0min);
    int ry1 = min(9, h - 1 - y0min);
    const float* f2base = g_f2l + g_lvloff[k] + (size_t)b * h * h * 256;

    for (int ry = ry0; ry <= ry1; ry++) {
        int yi = y0min + ry;
        const float* rowp = f2base + (size_t)yi * h * 256 + lane * 8;
#pragma unroll
        for (int rxp = 0; rxp < 5; rxp++) {
            int xi0 = x0min + rxp * 2;
            int xi1 = xi0 + 1;
            float d0 = 0.f, d1 = 0.f;
            if ((unsigned)xi0 < (unsigned)h) {
                const float4* q = reinterpret_cast<const float4*>(rowp + xi0 * 256);
                float4 b0 = q[0], b1 = q[1];
                float e0 = a0.x * b0.x + a0.y * b0.y;
                float e1 = a0.z * b0.z + a0.w * b0.w;
                e0 += a1.x * b1.x + a1.y * b1.y;
                e1 += a1.z * b1.z + a1.w * b1.w;
                d0 = e0 + e1;
            }
            if ((unsigned)xi1 < (unsigned)h) {
                const float4* q = reinterpret_cast<const float4*>(rowp + xi1 * 256);
                float4 b0 = q[0], b1 = q[1];
                float e0 = a0.x * b0.x + a0.y * b0.y;
                float e1 = a0.z * b0.z + a0.w * b0.w;
                e0 += a1.x * b1.x + a1.y * b1.y;
                e1 += a1.z * b1.z + a1.w * b1.w;
                d1 = e0 + e1;
            }
            // paired warp reduction: lane0 -> sum(d0), lane16 -> sum(d1)
            d0 += __shfl_xor_sync(0xffffffffu, d0, 16);
            d1 += __shfl_xor_sync(0xffffffffu, d1, 16);
            float z = (lane & 16) ? d1 : d0;
            z += __shfl_xor_sync(0xffffffffu, z, 8);
            z += __shfl_xor_sync(0xffffffffu, z, 4);
            z += __shfl_xor_sync(0xffffffffu, z, 2);
            z += __shfl_xor_sync(0xffffffffu, z, 1);
            if (lane == 0)  sw[ry * 10 + rxp * 2]     = z;
            if (lane == 16) sw[ry * 10 + rxp * 2 + 1] = z;
        }
    }
    __syncwarp();

    // bilinear combine: 41 samples, OOB corners are 0 in sw (zero padding)
    float* op = out + ((size_t)p * 4 + k) * 41;
    for (int si = lane; si < 41; si += 32) {
        float py = (yc + g_dy[si]) * sc;
        float px = (xc + g_dx[si]) * sc;
        float fy0 = floorf(py), fx0 = floorf(px);
        float wy1 = py - fy0, wx1 = px - fx0;
        float wy0 = 1.f - wy1, wx0 = 1.f - wx1;
        int ry = (int)fy0 - y0min;   // in [0,8] by construction
        int rx = (int)fx0 - x0min;
        float v00 = sw[ry * 10 + rx],      v01 = sw[ry * 10 + rx + 1];
        float v10 = sw[ry * 10 + rx + 10], v11 = sw[ry * 10 + rx + 11];
        op[si] = wy0 * (wx0 * v00 + wx1 * v01) + wy1 * (wx0 * v10 + wx1 * v11);
    }
}

// ---------------------------------------------------------------------------
extern "C" void kernel_launch(void* const* d_in, const int* in_sizes, int n_in,
                              void* d_out, int out_size) {
    const float* f1   = (const float*)d_in[0];
    const float* f2   = (const float*)d_in[1];
    const float* flow = (const float*)d_in[2];
    float* out = (float*)d_out;

    float *f1t_ptr, *f2l_ptr;
    cudaGetSymbolAddress((void**)&f1t_ptr, g_f1t);
    cudaGetSymbolAddress((void**)&f2l_ptr, g_f2l);

    // prep: channel-last transpose (f1 scaled by 1/sqrt(C)=1/16), f2 pyramid
    transpose_cl<<<1024, 256>>>(f1, f1t_ptr, 1.0f / 16.0f);
    transpose_cl<<<1024, 256>>>(f2, f2l_ptr, 1.0f);
    pool2<<<1024, 256>>>((const float4*)(f2l_ptr),
                         (float4*)(f2l_ptr + 4194304), 64, 262144);
    pool2<<<256, 256>>>((const float4*)(f2l_ptr + 4194304),
                        (float4*)(f2l_ptr + 5242880), 32, 65536);
    pool2<<<64, 256>>>((const float4*)(f2l_ptr + 5242880),
                       (float4*)(f2l_ptr + 5505024), 16, 16384);

    // main: 65536 (pixel, level) warps, 8 warps/block
    lookup_main<<<8192, 256>>>(flow, out);
}

// round 2
// speedup vs baseline: 1.0783x; 1.0783x over previous
#include <cuda_runtime.h>
#include <math.h>

// ---------------------------------------------------------------------------
// Lookup_8710193676603: RAFT correlation pyramid lookup.
// Identity: bilinear(pool_k(corr)) == dot(f1_pix, pool_k(f2)_corner)/16.
// Round 2: block = 4x4 pixel tile at ONE level (16 warps) so the f2 corner
// vectors loaded by different warps overlap ~90% and are served from L1.
// ---------------------------------------------------------------------------

#define NB 4
#define NC 256
#define NP 4096           // 64*64 pixels per batch

static __device__ float g_f1t[(size_t)NB * NP * NC];   // [B,64,64,C], pre-scaled by 1/16
static __device__ float g_f2l[5570560];                 // channel-last pyramid
__device__ const int g_lvloff[4] = {0, 4194304, 5242880, 5505024};

__device__ const float g_dy[41] = {
  -4.f,
  -3.f,-3.f,-3.f,
  -2.f,-2.f,-2.f,-2.f,-2.f,
  -1.f,-1.f,-1.f,-1.f,-1.f,-1.f,-1.f,
   0.f, 0.f, 0.f, 0.f, 0.f, 0.f, 0.f, 0.f, 0.f,
   1.f, 1.f, 1.f, 1.f, 1.f, 1.f, 1.f,
   2.f, 2.f, 2.f, 2.f, 2.f,
   3.f, 3.f, 3.f,
   4.f};
__device__ const float g_dx[41] = {
   0.f,
  -1.f, 0.f, 1.f,
  -2.f,-1.f, 0.f, 1.f, 2.f,
  -3.f,-2.f,-1.f, 0.f, 1.f, 2.f, 3.f,
  -4.f,-3.f,-2.f,-1.f, 0.f, 1.f, 2.f, 3.f, 4.f,
  -3.f,-2.f,-1.f, 0.f, 1.f, 2.f, 3.f,
  -2.f,-1.f, 0.f, 1.f, 2.f,
  -1.f, 0.f, 1.f,
   0.f};

// ---- transpose [B,C,64,64] -> [B,64,64,C], times scale ----------------------
__global__ void transpose_cl(const float* __restrict__ in, float* __restrict__ out,
                             float scale) {
    __shared__ float tile[64][65];
    int cc  = blockIdx.x & 3;
    int i   = (blockIdx.x >> 2) & 63;
    int b   = blockIdx.x >> 8;
    int tid = threadIdx.x;
#pragma unroll
    for (int t = 0; t < 16; t++) {
        int idx = tid + t * 256;
        int cl = idx >> 6, jj = idx & 63;
        tile[cl][jj] = in[(((b * 256 + cc * 64 + cl) * 64 + i) * 64) + jj] * scale;
    }
    __syncthreads();
#pragma unroll
    for (int t = 0; t < 16; t++) {
        int idx = tid + t * 256;
        int jj = idx >> 6, cl = idx & 63;
        out[((b * 64 + i) * 64 + jj) * 256 + cc * 64 + cl] = tile[cl][jj];
    }
}

// ---- 2x2 avg pool, channel-last, float4 -------------------------------------
__global__ void pool2(const float4* __restrict__ in, float4* __restrict__ out,
                      int hin, int total) {
    int idx = blockIdx.x * blockDim.x + threadIdx.x;
    if (idx >= total) return;
    int hout = hin >> 1;
    int c4 = idx & 63;
    int r  = idx >> 6;
    int x  = r % hout; r /= hout;
    int y  = r % hout;
    int b  = r / hout;
    const float4* p00 = in + (((size_t)(b * hin + 2 * y) * hin + 2 * x) * 64) + c4;
    const float4* p01 = p00 + 64;
    const float4* p10 = p00 + (size_t)hin * 64;
    const float4* p11 = p10 + 64;
    float4 a = *p00, bb = *p01, c = *p10, d = *p11, o;
    o.x = 0.25f * (a.x + bb.x + c.x + d.x);
    o.y = 0.25f * (a.y + bb.y + c.y + d.y);
    o.z = 0.25f * (a.z + bb.z + c.z + d.z);
    o.w = 0.25f * (a.w + bb.w + c.w + d.w);
    out[idx] = o;
}

// ---- main lookup: block = 4x4 pixel tile @ one level, one warp per pixel ----
__global__ __launch_bounds__(512) void lookup_main(const float* __restrict__ flow,
                                                   float* __restrict__ out) {
    __shared__ float sd[16][100];
    int lane = threadIdx.x & 31;
    int warp = threadIdx.x >> 5;

    int t  = blockIdx.x & 1023;     // tile id (within level)
    int k  = blockIdx.x >> 10;      // pyramid level
    int b  = t >> 8;
    int ty = (t >> 4) & 15;
    int tx = t & 15;
    int i  = ty * 4 + (warp >> 2);
    int j  = tx * 4 + (warp & 3);
    int p  = (b << 12) + (i << 6) + j;   // global pixel id

    // f1 fragment: lane holds channels [lane*8, lane*8+8)
    const float4* f1p = reinterpret_cast<const float4*>(g_f1t + (size_t)p * 256 + lane * 8);
    float4 a0 = f1p[0], a1 = f1p[1];

    float fy = flow[(b * 2 + 0) * 4096 + i * 64 + j];
    float fx = flow[(b * 2 + 1) * 4096 + i * 64 + j];
    int   h   = 64 >> k;
    float sc  = (float)(h - 1) / (float)h;
    float inv = 1.0f / (float)(1 << k);
    float yc = ((float)i + fy) * inv;
    float xc = ((float)j + fx) * inv;
    int y0min = (int)floorf((yc - 4.0f) * sc);
    int x0min = (int)floorf((xc - 4.0f) * sc);

    float* sw = sd[warp];
    sw[lane] = 0.f; sw[lane + 32] = 0.f; sw[lane + 64] = 0.f;
    if (lane < 4) sw[96 + lane] = 0.f;
    __syncwarp();

    int ry0 = max(0, -y0min);
    int ry1 = min(9, h - 1 - y0min);
    const float* f2base = g_f2l + g_lvloff[k] + (size_t)b * h * h * 256;

    for (int ry = ry0; ry <= ry1; ry++) {
        int yi = y0min + ry;
        const float* rowp = f2base + (size_t)yi * h * 256 + lane * 8;
#pragma unroll
        for (int rxp = 0; rxp < 5; rxp++) {
            int xi0 = x0min + rxp * 2;
            int xi1 = xi0 + 1;
            float d0 = 0.f, d1 = 0.f;
            if ((unsigned)xi0 < (unsigned)h) {
                const float4* q = reinterpret_cast<const float4*>(rowp + xi0 * 256);
                float4 b0 = q[0], b1 = q[1];
                float e0 = a0.x * b0.x + a0.y * b0.y;
                float e1 = a0.z * b0.z + a0.w * b0.w;
                e0 += a1.x * b1.x + a1.y * b1.y;
                e1 += a1.z * b1.z + a1.w * b1.w;
                d0 = e0 + e1;
            }
            if ((unsigned)xi1 < (unsigned)h) {
                const float4* q = reinterpret_cast<const float4*>(rowp + xi1 * 256);
                float4 b0 = q[0], b1 = q[1];
                float e0 = a0.x * b0.x + a0.y * b0.y;
                float e1 = a0.z * b0.z + a0.w * b0.w;
                e0 += a1.x * b1.x + a1.y * b1.y;
                e1 += a1.z * b1.z + a1.w * b1.w;
                d1 = e0 + e1;
            }
            // paired warp reduction: lane0 -> sum(d0), lane16 -> sum(d1)
            d0 += __shfl_xor_sync(0xffffffffu, d0, 16);
            d1 += __shfl_xor_sync(0xffffffffu, d1, 16);
            float z = (lane & 16) ? d1 : d0;
            z += __shfl_xor_sync(0xffffffffu, z, 8);
            z += __shfl_xor_sync(0xffffffffu, z, 4);
            z += __shfl_xor_sync(0xffffffffu, z, 2);
            z += __shfl_xor_sync(0xffffffffu, z, 1);
            if (lane == 0)  sw[ry * 10 + rxp * 2]     = z;
            if (lane == 16) sw[ry * 10 + rxp * 2 + 1] = z;
        }
    }
    __syncwarp();

    // bilinear combine: 41 samples, OOB corners are 0 in sw (zero padding)
    float* op = out + ((size_t)p * 4 + k) * 41;
    for (int si = lane; si < 41; si += 32) {
        float py = (yc + g_dy[si]) * sc;
        float px = (xc + g_dx[si]) * sc;
        float fy0 = floorf(py), fx0 = floorf(px);
        float wy1 = py - fy0, wx1 = px - fx0;
        float wy0 = 1.f - wy1, wx0 = 1.f - wx1;
        int ry = (int)fy0 - y0min;   // in [0,8] by construction
        int rx = (int)fx0 - x0min;
        float v00 = sw[ry * 10 + rx],      v01 = sw[ry * 10 + rx + 1];
        float v10 = sw[ry * 10 + rx + 10], v11 = sw[ry * 10 + rx + 11];
        op[si] = wy0 * (wx0 * v00 + wx1 * v01) + wy1 * (wx0 * v10 + wx1 * v11);
    }
}

// ---------------------------------------------------------------------------
extern "C" void kernel_launch(void* const* d_in, const int* in_sizes, int n_in,
                              void* d_out, int out_size) {
    const float* f1   = (const float*)d_in[0];
    const float* f2   = (const float*)d_in[1];
    const float* flow = (const float*)d_in[2];
    float* out = (float*)d_out;

    float *f1t_ptr, *f2l_ptr;
    cudaGetSymbolAddress((void**)&f1t_ptr, g_f1t);
    cudaGetSymbolAddress((void**)&f2l_ptr, g_f2l);

    transpose_cl<<<1024, 256>>>(f1, f1t_ptr, 1.0f / 16.0f);
    transpose_cl<<<1024, 256>>>(f2, f2l_ptr, 1.0f);
    pool2<<<1024, 256>>>((const float4*)(f2l_ptr),
                         (float4*)(f2l_ptr + 4194304), 64, 262144);
    pool2<<<256, 256>>>((const float4*)(f2l_ptr + 4194304),
                        (float4*)(f2l_ptr + 5242880), 32, 65536);
    pool2<<<64, 256>>>((const float4*)(f2l_ptr + 5242880),
                       (float4*)(f2l_ptr + 5505024), 16, 16384);

    // main: 1024 tiles (4x4 px) x 4 levels, 16 warps/block (one per pixel)
    lookup_main<<<4096, 512>>>(flow, out);
}

// round 4
// speedup vs baseline: 1.9310x; 1.7907x over previous
#include <cuda_runtime.h>
#include <math.h>

// ---------------------------------------------------------------------------
// Lookup_8710193676603: RAFT correlation pyramid lookup.
// Identity: bilinear(pool_k(corr)) == dot(f1_pix, pool_k(f2)_corner)/16.
// Round 4: warp = 2x2 pixel group at one level; f1 x4 register-resident, each
// f2 corner vector loaded once and reused for 4 dots over the union window.
// Fused 4-way butterfly reduction (sm_103 has no redux.f32).
// ---------------------------------------------------------------------------

#define NB 4
#define NC 256
#define NP 4096

static __device__ float g_f1t[(size_t)NB * NP * NC];   // [B,64,64,C], pre-scaled by 1/16
static __device__ float g_f2l[5570560];                 // channel-last pyramid
__device__ const int g_lvloff[4] = {0, 4194304, 5242880, 5505024};

__device__ const float g_dy[41] = {
  -4.f,
  -3.f,-3.f,-3.f,
  -2.f,-2.f,-2.f,-2.f,-2.f,
  -1.f,-1.f,-1.f,-1.f,-1.f,-1.f,-1.f,
   0.f, 0.f, 0.f, 0.f, 0.f, 0.f, 0.f, 0.f, 0.f,
   1.f, 1.f, 1.f, 1.f, 1.f, 1.f, 1.f,
   2.f, 2.f, 2.f, 2.f, 2.f,
   3.f, 3.f, 3.f,
   4.f};
__device__ const float g_dx[41] = {
   0.f,
  -1.f, 0.f, 1.f,
  -2.f,-1.f, 0.f, 1.f, 2.f,
  -3.f,-2.f,-1.f, 0.f, 1.f, 2.f, 3.f,
  -4.f,-3.f,-2.f,-1.f, 0.f, 1.f, 2.f, 3.f, 4.f,
  -3.f,-2.f,-1.f, 0.f, 1.f, 2.f, 3.f,
  -2.f,-1.f, 0.f, 1.f, 2.f,
  -1.f, 0.f, 1.f,
   0.f};

// ---- transpose [B,C,64,64] -> [B,64,64,C], times scale ----------------------
__global__ void transpose_cl(const float* __restrict__ in, float* __restrict__ out,
                             float scale) {
    __shared__ float tile[64][65];
    int cc  = blockIdx.x & 3;
    int i   = (blockIdx.x >> 2) & 63;
    int b   = blockIdx.x >> 8;
    int tid = threadIdx.x;
#pragma unroll
    for (int t = 0; t < 16; t++) {
        int idx = tid + t * 256;
        int cl = idx >> 6, jj = idx & 63;
        tile[cl][jj] = in[(((b * 256 + cc * 64 + cl) * 64 + i) * 64) + jj] * scale;
    }
    __syncthreads();
#pragma unroll
    for (int t = 0; t < 16; t++) {
        int idx = tid + t * 256;
        int jj = idx >> 6, cl = idx & 63;
        out[((b * 64 + i) * 64 + jj) * 256 + cc * 64 + cl] = tile[cl][jj];
    }
}

// ---- 2x2 avg pool, channel-last, float4 -------------------------------------
__global__ void pool2(const float4* __restrict__ in, float4* __restrict__ out,
                      int hin, int total) {
    int idx = blockIdx.x * blockDim.x + threadIdx.x;
    if (idx >= total) return;
    int hout = hin >> 1;
    int c4 = idx & 63;
    int r  = idx >> 6;
    int x  = r % hout; r /= hout;
    int y  = r % hout;
    int b  = r / hout;
    const float4* p00 = in + (((size_t)(b * hin + 2 * y) * hin + 2 * x) * 64) + c4;
    const float4* p01 = p00 + 64;
    const float4* p10 = p00 + (size_t)hin * 64;
    const float4* p11 = p10 + 64;
    float4 a = *p00, bb = *p01, c = *p10, d = *p11, o;
    o.x = 0.25f * (a.x + bb.x + c.x + d.x);
    o.y = 0.25f * (a.y + bb.y + c.y + d.y);
    o.z = 0.25f * (a.z + bb.z + c.z + d.z);
    o.w = 0.25f * (a.w + bb.w + c.w + d.w);
    out[idx] = o;
}

// ---- main lookup: warp = 2x2 pixel group @ one level ------------------------
__global__ __launch_bounds__(256) void lookup_main(const float* __restrict__ flow,
                                                   float* __restrict__ out) {
    __shared__ float sd[8][4][100];   // [warp][pixel][10x10 corner grid]
    int lane = threadIdx.x & 31;
    int warp = threadIdx.x >> 5;

    int k  = blockIdx.x >> 9;                       // level (512 blocks/level)
    int gg = ((blockIdx.x & 511) << 3) + warp;      // group id, 4096/level
    int b  = gg >> 10;
    int gy = (gg >> 5) & 31;
    int gx = gg & 31;
    int i0 = gy * 2, j0 = gx * 2;

    int   h   = 64 >> k;
    float sc  = (float)(h - 1) / (float)h;
    float inv = 1.0f / (float)(1 << k);

    // per-pixel register f1 fragments + window params
    float4 a00, a01, a10, a11, a20, a21, a30, a31;
    float yc[4], xc[4];
    int y0[4], x0[4];
    {
        int p0 = (b << 12) + (i0 << 6) + j0;
        const float4* f0  = reinterpret_cast<const float4*>(g_f1t + (size_t)p0 * 256 + lane * 8);
        const float4* f1p = reinterpret_cast<const float4*>(g_f1t + (size_t)(p0 + 1) * 256 + lane * 8);
        const float4* f2p = reinterpret_cast<const float4*>(g_f1t + (size_t)(p0 + 64) * 256 + lane * 8);
        const float4* f3p = reinterpret_cast<const float4*>(g_f1t + (size_t)(p0 + 65) * 256 + lane * 8);
        a00 = f0[0];  a01 = f0[1];
        a10 = f1p[0]; a11 = f1p[1];
        a20 = f2p[0]; a21 = f2p[1];
        a30 = f3p[0]; a31 = f3p[1];
    }
#pragma unroll
    for (int pp = 0; pp < 4; pp++) {
        int i = i0 + (pp >> 1), j = j0 + (pp & 1);
        float fy = flow[(b * 2 + 0) * 4096 + i * 64 + j];
        float fx = flow[(b * 2 + 1) * 4096 + i * 64 + j];
        yc[pp] = ((float)i + fy) * inv;
        xc[pp] = ((float)j + fx) * inv;
        y0[pp] = (int)floorf((yc[pp] - 4.0f) * sc);
        x0[pp] = (int)floorf((xc[pp] - 4.0f) * sc);
    }

    // zero corner grids (zero padding for OOB)
    float* swf = &sd[warp][0][0];
    for (int t = lane; t < 400; t += 32) swf[t] = 0.f;
    __syncwarp();

    int uy0 = max(min(min(y0[0], y0[1]), min(y0[2], y0[3])), 0);
    int uy1 = min(max(max(y0[0], y0[1]), max(y0[2], y0[3])) + 9, h - 1);
    int ux0 = max(min(min(x0[0], x0[1]), min(x0[2], x0[3])), 0);
    int ux1 = min(max(max(x0[0], x0[1]), max(x0[2], x0[3])) + 9, h - 1);

    const float* f2base = g_f2l + g_lvloff[k] + (size_t)b * h * h * 256 + lane * 8;

    // lane's pixel for the fused reduction result: lane0->p0, 16->p1, 8->p2, 24->p3
    int myp  = ((lane & 16) ? 1 : 0) | ((lane & 8) ? 2 : 0);
    int myy0 = y0[myp], myx0 = x0[myp];
    bool amWriter = (lane & 7) == 0;
    float* mysw = &sd[warp][myp][0];

    for (int yi = uy0; yi <= uy1; yi++) {
        const float* rowp = f2base + (size_t)yi * h * 256;
        int  myry = yi - myy0;
        bool okRow = amWriter && (unsigned)myry < 10u;
        for (int xi = ux0; xi <= ux1; xi++) {
            const float4* q = reinterpret_cast<const float4*>(rowp + xi * 256);
            float4 b0 = q[0], b1 = q[1];
            float d0 = b0.x * a00.x + b0.y * a00.y + b0.z * a00.z + b0.w * a00.w
                     + b1.x * a01.x + b1.y * a01.y + b1.z * a01.z + b1.w * a01.w;
            float d1 = b0.x * a10.x + b0.y * a10.y + b0.z * a10.z + b0.w * a10.w
                     + b1.x * a11.x + b1.y * a11.y + b1.z * a11.z + b1.w * a11.w;
            float d2 = b0.x * a20.x + b0.y * a20.y + b0.z * a20.z + b0.w * a20.w
                     + b1.x * a21.x + b1.y * a21.y + b1.z * a21.z + b1.w * a21.w;
            float d3 = b0.x * a30.x + b0.y * a30.y + b0.z * a30.z + b0.w * a30.w
                     + b1.x * a31.x + b1.y * a31.y + b1.z * a31.z + b1.w * a31.w;
            // fused 4-way butterfly: results land at lanes 0(p0),16(p1),8(p2),24(p3)
            d0 += __shfl_xor_sync(0xffffffffu, d0, 16);
            d1 += __shfl_xor_sync(0xffffffffu, d1, 16);
            d2 += __shfl_xor_sync(0xffffffffu, d2, 16);
            d3 += __shfl_xor_sync(0xffffffffu, d3, 16);
            float za = (lane & 16) ? d1 : d0;
            float zb = (lane & 16) ? d3 : d2;
            za += __shfl_xor_sync(0xffffffffu, za, 8);
            zb += __shfl_xor_sync(0xffffffffu, zb, 8);
            float z = (lane & 8) ? zb : za;
            z += __shfl_xor_sync(0xffffffffu, z, 4);
            z += __shfl_xor_sync(0xffffffffu, z, 2);
            z += __shfl_xor_sync(0xffffffffu, z, 1);
            int myrx = xi - myx0;
            if (okRow && (unsigned)myrx < 10u) mysw[myry * 10 + myrx] = z;
        }
    }
    __syncwarp();

    // bilinear combine: 4 pixels x 41 samples
#pragma unroll
    for (int pp = 0; pp < 4; pp++) {
        int i = i0 + (pp >> 1), j = j0 + (pp & 1);
        int p = (b << 12) + (i << 6) + j;
        float* op = out + ((size_t)p * 4 + k) * 41;
        const float* sw = &sd[warp][pp][0];
        float ycp = yc[pp], xcp = xc[pp];
        int y0p = y0[pp], x0p = x0[pp];
        for (int si = lane; si < 41; si += 32) {
            float py = (ycp + g_dy[si]) * sc;
            float px = (xcp + g_dx[si]) * sc;
            float fy0 = floorf(py), fx0 = floorf(px);
            float wy1 = py - fy0, wx1 = px - fx0;
            float wy0 = 1.f - wy1, wx0 = 1.f - wx1;
            int ry = (int)fy0 - y0p;
            int rx = (int)fx0 - x0p;
            float v00 = sw[ry * 10 + rx],      v01 = sw[ry * 10 + rx + 1];
            float v10 = sw[ry * 10 + rx + 10], v11 = sw[ry * 10 + rx + 11];
            op[si] = wy0 * (wx0 * v00 + wx1 * v01) + wy1 * (wx0 * v10 + wx1 * v11);
        }
    }
}

// ---------------------------------------------------------------------------
extern "C" void kernel_launch(void* const* d_in, const int* in_sizes, int n_in,
                              void* d_out, int out_size) {
    const float* f1   = (const float*)d_in[0];
    const float* f2   = (const float*)d_in[1];
    const float* flow = (const float*)d_in[2];
    float* out = (float*)d_out;

    float *f1t_ptr, *f2l_ptr;
    cudaGetSymbolAddress((void**)&f1t_ptr, g_f1t);
    cudaGetSymbolAddress((void**)&f2l_ptr, g_f2l);

    transpose_cl<<<1024, 256>>>(f1, f1t_ptr, 1.0f / 16.0f);
    transpose_cl<<<1024, 256>>>(f2, f2l_ptr, 1.0f);
    pool2<<<1024, 256>>>((const float4*)(f2l_ptr),
                         (float4*)(f2l_ptr + 4194304), 64, 262144);
    pool2<<<256, 256>>>((const float4*)(f2l_ptr + 4194304),
                        (float4*)(f2l_ptr + 5242880), 32, 65536);
    pool2<<<64, 256>>>((const float4*)(f2l_ptr + 5242880),
                       (float4*)(f2l_ptr + 5505024), 16, 16384);

    // main: 4 levels x 512 blocks, 8 warps/block, warp = 2x2 pixel group
    lookup_main<<<2048, 256>>>(flow, out);
}

// round 5
// speedup vs baseline: 2.3401x; 1.2118x over previous
#include <cuda_runtime.h>
#include <math.h>

// ---------------------------------------------------------------------------
// Lookup_8710193676603: RAFT correlation pyramid lookup.
// Identity: bilinear(pool_k(corr)) == dot(f1_pix, pool_k(f2)_corner)/16.
// Round 5: same 2x2-pixel-group algorithm as round 4, but:
//  - corner loads are fully coalesced (lane l reads ch [4l,4l+4) and
//    [128+4l,128+4l+4)): 2x LDG.128 of 512B each -> 1.0 cyc/wavefront
//    instead of the 8-line divergent pattern's 2.07 cyc replay wavefronts.
//  - dot products use packed fma.rn.f32x2 (FFMA2), halving FMA-pipe load.
// ---------------------------------------------------------------------------

#define NB 4
#define NC 256
#define NP 4096

typedef unsigned long long u64;

static __device__ float g_f1t[(size_t)NB * NP * NC];   // [B,64,64,C], pre-scaled by 1/16
static __device__ float g_f2l[5570560];                 // channel-last pyramid
__device__ const int g_lvloff[4] = {0, 4194304, 5242880, 5505024};

__device__ const float g_dy[41] = {
  -4.f,
  -3.f,-3.f,-3.f,
  -2.f,-2.f,-2.f,-2.f,-2.f,
  -1.f,-1.f,-1.f,-1.f,-1.f,-1.f,-1.f,
   0.f, 0.f, 0.f, 0.f, 0.f, 0.f, 0.f, 0.f, 0.f,
   1.f, 1.f, 1.f, 1.f, 1.f, 1.f, 1.f,
   2.f, 2.f, 2.f, 2.f, 2.f,
   3.f, 3.f, 3.f,
   4.f};
__device__ const float g_dx[41] = {
   0.f,
  -1.f, 0.f, 1.f,
  -2.f,-1.f, 0.f, 1.f, 2.f,
  -3.f,-2.f,-1.f, 0.f, 1.f, 2.f, 3.f,
  -4.f,-3.f,-2.f,-1.f, 0.f, 1.f, 2.f, 3.f, 4.f,
  -3.f,-2.f,-1.f, 0.f, 1.f, 2.f, 3.f,
  -2.f,-1.f, 0.f, 1.f, 2.f,
  -1.f, 0.f, 1.f,
   0.f};

__device__ __forceinline__ u64 ffma2(u64 a, u64 b, u64 c) {
    u64 r;
    asm("fma.rn.f32x2 %0, %1, %2, %3;" : "=l"(r) : "l"(a), "l"(b), "l"(c));
    return r;
}
__device__ __forceinline__ float hadd2(u64 v) {
    float lo, hi;
    asm("mov.b64 {%0, %1}, %2;" : "=f"(lo), "=f"(hi) : "l"(v));
    return lo + hi;
}

// ---- transpose [B,C,64,64] -> [B,64,64,C], times scale ----------------------
__global__ void transpose_cl(const float* __restrict__ in, float* __restrict__ out,
                             float scale) {
    __shared__ float tile[64][65];
    int cc  = blockIdx.x & 3;
    int i   = (blockIdx.x >> 2) & 63;
    int b   = blockIdx.x >> 8;
    int tid = threadIdx.x;
#pragma unroll
    for (int t = 0; t < 16; t++) {
        int idx = tid + t * 256;
        int cl = idx >> 6, jj = idx & 63;
        tile[cl][jj] = in[(((b * 256 + cc * 64 + cl) * 64 + i) * 64) + jj] * scale;
    }
    __syncthreads();
#pragma unroll
    for (int t = 0; t < 16; t++) {
        int idx = tid + t * 256;
        int jj = idx >> 6, cl = idx & 63;
        out[((b * 64 + i) * 64 + jj) * 256 + cc * 64 + cl] = tile[cl][jj];
    }
}

// ---- 2x2 avg pool, channel-last, float4 -------------------------------------
__global__ void pool2(const float4* __restrict__ in, float4* __restrict__ out,
                      int hin, int total) {
    int idx = blockIdx.x * blockDim.x + threadIdx.x;
    if (idx >= total) return;
    int hout = hin >> 1;
    int c4 = idx & 63;
    int r  = idx >> 6;
    int x  = r % hout; r /= hout;
    int y  = r % hout;
    int b  = r / hout;
    const float4* p00 = in + (((size_t)(b * hin + 2 * y) * hin + 2 * x) * 64) + c4;
    const float4* p01 = p00 + 64;
    const float4* p10 = p00 + (size_t)hin * 64;
    const float4* p11 = p10 + 64;
    float4 a = *p00, bb = *p01, c = *p10, d = *p11, o;
    o.x = 0.25f * (a.x + bb.x + c.x + d.x);
    o.y = 0.25f * (a.y + bb.y + c.y + d.y);
    o.z = 0.25f * (a.z + bb.z + c.z + d.z);
    o.w = 0.25f * (a.w + bb.w + c.w + d.w);
    out[idx] = o;
}

// ---- main lookup: warp = 2x2 pixel group @ one level ------------------------
__global__ __launch_bounds__(256) void lookup_main(const float* __restrict__ flow,
                                                   float* __restrict__ out) {
    __shared__ float sd[8][4][100];   // [warp][pixel][10x10 corner grid]
    int lane = threadIdx.x & 31;
    int warp = threadIdx.x >> 5;

    int k  = blockIdx.x >> 9;                       // level (512 blocks/level)
    int gg = ((blockIdx.x & 511) << 3) + warp;      // group id, 4096/level
    int b  = gg >> 10;
    int gy = (gg >> 5) & 31;
    int gx = gg & 31;
    int i0 = gy * 2, j0 = gx * 2;

    int   h   = 64 >> k;
    float sc  = (float)(h - 1) / (float)h;
    float inv = 1.0f / (float)(1 << k);

    // per-pixel register f1 fragments (packed f32x2 pairs) + window params
    // lane holds channels [4*lane, 4*lane+4) and [128+4*lane, 128+4*lane+4)
    ulonglong2 aL[4], aH[4];
    float yc[4], xc[4];
    int y0[4], x0[4];
    {
        int p0 = (b << 12) + (i0 << 6) + j0;
        const int dp[4] = {0, 1, 64, 65};
#pragma unroll
        for (int pp = 0; pp < 4; pp++) {
            const float* fp = g_f1t + (size_t)(p0 + dp[pp]) * 256;
            aL[pp] = *reinterpret_cast<const ulonglong2*>(fp + lane * 4);
            aH[pp] = *reinterpret_cast<const ulonglong2*>(fp + 128 + lane * 4);
        }
    }
#pragma unroll
    for (int pp = 0; pp < 4; pp++) {
        int i = i0 + (pp >> 1), j = j0 + (pp & 1);
        float fy = flow[(b * 2 + 0) * 4096 + i * 64 + j];
        float fx = flow[(b * 2 + 1) * 4096 + i * 64 + j];
        yc[pp] = ((float)i + fy) * inv;
        xc[pp] = ((float)j + fx) * inv;
        y0[pp] = (int)floorf((yc[pp] - 4.0f) * sc);
        x0[pp] = (int)floorf((xc[pp] - 4.0f) * sc);
    }

    // zero corner grids (zero padding for OOB)
    float* swf = &sd[warp][0][0];
    for (int t = lane; t < 400; t += 32) swf[t] = 0.f;
    __syncwarp();

    int uy0 = max(min(min(y0[0], y0[1]), min(y0[2], y0[3])), 0);
    int uy1 = min(max(max(y0[0], y0[1]), max(y0[2], y0[3])) + 9, h - 1);
    int ux0 = max(min(min(x0[0], x0[1]), min(x0[2], x0[3])), 0);
    int ux1 = min(max(max(x0[0], x0[1]), max(x0[2], x0[3])) + 9, h - 1);

    const float* f2base = g_f2l + g_lvloff[k] + (size_t)b * h * h * 256 + lane * 4;

    // lane's pixel for the fused reduction result: lane0->p0, 16->p1, 8->p2, 24->p3
    int myp  = ((lane & 16) ? 1 : 0) | ((lane & 8) ? 2 : 0);
    int myy0 = y0[myp], myx0 = x0[myp];
    bool amWriter = (lane & 7) == 0;
    float* mysw = &sd[warp][myp][0];

    for (int yi = uy0; yi <= uy1; yi++) {
        const float* rowp = f2base + (size_t)yi * h * 256;
        int  myry = yi - myy0;
        bool okRow = amWriter && (unsigned)myry < 10u;
        for (int xi = ux0; xi <= ux1; xi++) {
            // coalesced: lanes read 512B consecutive per LDG.128
            ulonglong2 bL = *reinterpret_cast<const ulonglong2*>(rowp + xi * 256);
            ulonglong2 bH = *reinterpret_cast<const ulonglong2*>(rowp + xi * 256 + 128);
            u64 c0 = ffma2(bL.x, aL[0].x, ffma2(bL.y, aL[0].y,
                     ffma2(bH.x, aH[0].x, ffma2(bH.y, aH[0].y, 0ull))));
            u64 c1 = ffma2(bL.x, aL[1].x, ffma2(bL.y, aL[1].y,
                     ffma2(bH.x, aH[1].x, ffma2(bH.y, aH[1].y, 0ull))));
            u64 c2 = ffma2(bL.x, aL[2].x, ffma2(bL.y, aL[2].y,
                     ffma2(bH.x, aH[2].x, ffma2(bH.y, aH[2].y, 0ull))));
            u64 c3 = ffma2(bL.x, aL[3].x, ffma2(bL.y, aL[3].y,
                     ffma2(bH.x, aH[3].x, ffma2(bH.y, aH[3].y, 0ull))));
            float d0 = hadd2(c0), d1 = hadd2(c1), d2 = hadd2(c2), d3 = hadd2(c3);
            // fused 4-way butterfly: results land at lanes 0(p0),16(p1),8(p2),24(p3)
            d0 += __shfl_xor_sync(0xffffffffu, d0, 16);
            d1 += __shfl_xor_sync(0xffffffffu, d1, 16);
            d2 += __shfl_xor_sync(0xffffffffu, d2, 16);
            d3 += __shfl_xor_sync(0xffffffffu, d3, 16);
            float za = (lane & 16) ? d1 : d0;
            float zb = (lane & 16) ? d3 : d2;
            za += __shfl_xor_sync(0xffffffffu, za, 8);
            zb += __shfl_xor_sync(0xffffffffu, zb, 8);
            float z = (lane & 8) ? zb : za;
            z += __shfl_xor_sync(0xffffffffu, z, 4);
            z += __shfl_xor_sync(0xffffffffu, z, 2);
            z += __shfl_xor_sync(0xffffffffu, z, 1);
            int myrx = xi - myx0;
            if (okRow && (unsigned)myrx < 10u) mysw[myry * 10 + myrx] = z;
        }
    }
    __syncwarp();

    // bilinear combine: 4 pixels x 41 samples
#pragma unroll
    for (int pp = 0; pp < 4; pp++) {
        int i = i0 + (pp >> 1), j = j0 + (pp & 1);
        int p = (b << 12) + (i << 6) + j;
        float* op = out + ((size_t)p * 4 + k) * 41;
        const float* sw = &sd[warp][pp][0];
        float ycp = yc[pp], xcp = xc[pp];
        int y0p = y0[pp], x0p = x0[pp];
        for (int si = lane; si < 41; si += 32) {
            float py = (ycp + g_dy[si]) * sc;
            float px = (xcp + g_dx[si]) * sc;
            float fy0 = floorf(py), fx0 = floorf(px);
            float wy1 = py - fy0, wx1 = px - fx0;
            float wy0 = 1.f - wy1, wx0 = 1.f - wx1;
            int ry = (int)fy0 - y0p;
            int rx = (int)fx0 - x0p;
            float v00 = sw[ry * 10 + rx],      v01 = sw[ry * 10 + rx + 1];
            float v10 = sw[ry * 10 + rx + 10], v11 = sw[ry * 10 + rx + 11];
            op[si] = wy0 * (wx0 * v00 + wx1 * v01) + wy1 * (wx0 * v10 + wx1 * v11);
        }
    }
}

// ---------------------------------------------------------------------------
extern "C" void kernel_launch(void* const* d_in, const int* in_sizes, int n_in,
                              void* d_out, int out_size) {
    const float* f1   = (const float*)d_in[0];
    const float* f2   = (const float*)d_in[1];
    const float* flow = (const float*)d_in[2];
    float* out = (float*)d_out;

    float *f1t_ptr, *f2l_ptr;
    cudaGetSymbolAddress((void**)&f1t_ptr, g_f1t);
    cudaGetSymbolAddress((void**)&f2l_ptr, g_f2l);

    transpose_cl<<<1024, 256>>>(f1, f1t_ptr, 1.0f / 16.0f);
    transpose_cl<<<1024, 256>>>(f2, f2l_ptr, 1.0f);
    pool2<<<1024, 256>>>((const float4*)(f2l_ptr),
                         (float4*)(f2l_ptr + 4194304), 64, 262144);
    pool2<<<256, 256>>>((const float4*)(f2l_ptr + 4194304),
                        (float4*)(f2l_ptr + 5242880), 32, 65536);
    pool2<<<64, 256>>>((const float4*)(f2l_ptr + 5242880),
                       (float4*)(f2l_ptr + 5505024), 16, 16384);

    // main: 4 levels x 512 blocks, 8 warps/block, warp = 2x2 pixel group
    lookup_main<<<2048, 256>>>(flow, out);
}